// round 10
// baseline (speedup 1.0000x reference)
#include <cuda_runtime.h>
#include <cstddef>

typedef unsigned long long ull;

#define CB 256
#define CS 128
#define CT 128
#define CE 512
#define CH 1024
#define CHD 512
#define CV 256
#define MK (CS*CB)
#define KC 32

#define OFF_XEMB   ((size_t)0)
#define OFF_PREA   (OFF_XEMB + (size_t)MK*CE)
#define OFF_PREB   (OFF_PREA + (size_t)MK*2048)
#define OFF_X1     (OFF_PREB + (size_t)MK*2048)
#define OFF_ENCOUT (OFF_X1 + (size_t)MK*CH)
#define OFF_ENCPROJ (OFF_ENCOUT + (size_t)MK*CH)
#define OFF_C0F    (OFF_ENCPROJ + (size_t)MK*CH)
#define OFF_C0B    (OFF_C0F + (size_t)CB*CHD)
#define OFF_C1F    (OFF_C0B + (size_t)CB*CHD)
#define OFF_C1B    (OFF_C1F + (size_t)CB*CHD)
#define OFF_DH0    (OFF_C1B + (size_t)CB*CHD)
#define OFF_DC0    (OFF_DH0 + (size_t)2*CB*CH)
#define OFF_DH1    (OFF_DC0 + (size_t)CB*CH)
#define OFF_DC1    (OFF_DH1 + (size_t)2*CB*CH)
#define OFF_Q      (OFF_DC1 + (size_t)CB*CH)
#define OFF_RIN    (OFF_Q + (size_t)CB*CH)
#define SCRATCH_FLOATS (OFF_RIN + (size_t)CB*(CE+CH))

__device__ float g_s[SCRATCH_FLOATS];
__device__ unsigned g_cnt;   // zero-init
__device__ unsigned g_gen;   // zero-init, monotonic across replays

#define FMA2(d,a,b,c) asm("fma.rn.f32x2 %0, %1, %2, %3;" : "=l"(d) : "l"(a), "l"(b), "l"(c))

__device__ __forceinline__ void upk(ull v, float& lo, float& hi){
    asm("mov.b64 {%0,%1}, %2;" : "=f"(lo), "=f"(hi) : "l"(v));
}

// accurate fast tanh (XLA rational, ~1e-7 abs err)
__device__ __forceinline__ float tanh_acc(float x){
    float xc = fminf(fmaxf(x, -7.90531110763549805f), 7.90531110763549805f);
    float x2 = xc*xc;
    float p = fmaf(x2, -2.76076847742355e-16f, 2.00018790482477e-13f);
    p = fmaf(x2, p, -8.60467152213735e-11f);
    p = fmaf(x2, p, 5.12229709037114e-08f);
    p = fmaf(x2, p, 1.48572235717979e-05f);
    p = fmaf(x2, p, 6.37261928875436e-04f);
    p = fmaf(x2, p, 4.89352455891786e-03f);
    p = p*xc;
    float q = fmaf(x2, 1.19825839466702e-06f, 1.18534705686654e-04f);
    q = fmaf(x2, q, 2.26843463243900e-03f);
    q = fmaf(x2, q, 4.89352518554385e-03f);
    return __fdividef(p, q);
}
__device__ __forceinline__ float sgf(float x){
    return __fdividef(1.f, 1.f + __expf(-x));
}

// ---- software grid barrier ----
__device__ __forceinline__ void gbar()
{
    __syncthreads();
    if (threadIdx.x == 0) {
        __threadfence();
        unsigned gen = atomicAdd(&g_gen, 0u);
        if (atomicAdd(&g_cnt, 1u) == gridDim.x - 1u) {
            atomicExch(&g_cnt, 0u);
            __threadfence();
            atomicAdd(&g_gen, 1u);
        } else {
            while (atomicAdd(&g_gen, 0u) == gen) __nanosleep(256);
        }
        __threadfence();
    }
    __syncthreads();
}

// ============ broadcast GEMM tile: 64n x 32m, C = A.W^T + bias ============
// A[m][k] lda, W[n][k] ldb, thread: tx=n-lane(32) x 2 strips, ty=m-oct(8) -> 4 m as 2 f32x2
__device__ __forceinline__ void gemm_core(
    const float* __restrict__ A, int lda,
    const float* __restrict__ W, int ldb, int K,
    const float* __restrict__ bias, float* __restrict__ C, long long ldc,
    int mBase, int nBase, float2* smw, float* smh)
{
    int tid = threadIdx.x, tx = tid & 31, ty = tid >> 5;
    ull acc[2][2] = {};
    for (int k0 = 0; k0 < K; k0 += KC) {
        {
            int fid = tid;            // 512 float4 total, 2 per thread
#pragma unroll
            for (int i = 0; i < 2; i++) {
                int s = fid >> 8, r = (fid >> 3) & 31, q = fid & 7;
                float4 v = *(const float4*)(W + (size_t)(nBase + s*32 + r)*ldb + k0 + 4*q);
                float2* d0 = smw + (s*KC + 4*q)*33 + r;
                d0[0]  = make_float2(v.x, v.x);
                d0[33] = make_float2(v.y, v.y);
                d0[66] = make_float2(v.z, v.z);
                d0[99] = make_float2(v.w, v.w);
                fid += 256;
            }
            int r = tid >> 3, q = tid & 7;
            float4 v = *(const float4*)(A + (size_t)(mBase + r)*lda + k0 + 4*q);
            smh[(4*q+0)*34 + r] = v.x;
            smh[(4*q+1)*34 + r] = v.y;
            smh[(4*q+2)*34 + r] = v.z;
            smh[(4*q+3)*34 + r] = v.w;
        }
        __syncthreads();
#pragma unroll 8
        for (int kk = 0; kk < KC; kk++) {
            ull h0 = *(const ull*)(smh + kk*34 + ty*4);
            ull h1 = *(const ull*)(smh + kk*34 + ty*4 + 2);
#pragma unroll
            for (int s = 0; s < 2; s++) {
                ull w = *(const ull*)&smw[(s*KC + kk)*33 + tx];
                FMA2(acc[s][0], w, h0, acc[s][0]);
                FMA2(acc[s][1], w, h1, acc[s][1]);
            }
        }
        __syncthreads();
    }
#pragma unroll
    for (int s = 0; s < 2; s++) {
        int n = nBase + s*32 + tx;
        float bz = bias ? bias[n] : 0.f;
#pragma unroll
        for (int p = 0; p < 2; p++) {
            float lo, hi; upk(acc[s][p], lo, hi);
            long long m = mBase + ty*4 + 2*p;
            C[m*ldc + n]     = lo + bz;
            C[(m+1)*ldc + n] = hi + bz;
        }
    }
}

// ============ fused LSTM cell tile: 32j x 32b, all 4 gates ============
// gates = A1@W1^T + A2@W2^T (+pre)(+bias); epilogue writes c, hout.
__device__ __forceinline__ void cell_core(
    const float* __restrict__ A1, int lda1, int K1, const float* __restrict__ W1,
    const float* __restrict__ A2, int lda2, int K2, const float* __restrict__ W2,
    const float* __restrict__ pre, const float* __restrict__ bias, int HID,
    float* __restrict__ c, float* __restrict__ hout, long long hStride,
    int jBase, int bBase, bool firstC, float2* smw, float* smh)
{
    int tid = threadIdx.x, tx = tid & 31, ty = tid >> 5;
    ull acc[4][2] = {};
#pragma unroll 1
    for (int seg = 0; seg < 2; seg++) {
        const float* A = seg ? A2 : A1;
        const float* W = seg ? W2 : W1;
        int K   = seg ? K2 : K1;
        int lda = seg ? lda2 : lda1;
        if (!A) continue;
        for (int k0 = 0; k0 < K; k0 += KC) {
            {
                int fid = tid;        // 1024 float4 total, 4 per thread
#pragma unroll
                for (int i = 0; i < 4; i++) {
                    int g = fid >> 8, r = (fid >> 3) & 31, q = fid & 7;
                    float4 v = *(const float4*)(W + (size_t)(g*HID + jBase + r)*K + k0 + 4*q);
                    float2* d0 = smw + (g*KC + 4*q)*33 + r;
                    d0[0]  = make_float2(v.x, v.x);
                    d0[33] = make_float2(v.y, v.y);
                    d0[66] = make_float2(v.z, v.z);
                    d0[99] = make_float2(v.w, v.w);
                    fid += 256;
                }
                int r = tid >> 3, q = tid & 7;
                float4 v = *(const float4*)(A + (size_t)(bBase + r)*lda + k0 + 4*q);
                smh[(4*q+0)*34 + r] = v.x;
                smh[(4*q+1)*34 + r] = v.y;
                smh[(4*q+2)*34 + r] = v.z;
                smh[(4*q+3)*34 + r] = v.w;
            }
            __syncthreads();
#pragma unroll 8
            for (int kk = 0; kk < KC; kk++) {
                ull h0 = *(const ull*)(smh + kk*34 + ty*4);
                ull h1 = *(const ull*)(smh + kk*34 + ty*4 + 2);
#pragma unroll
                for (int g = 0; g < 4; g++) {
                    ull w = *(const ull*)&smw[(g*KC + kk)*33 + tx];
                    FMA2(acc[g][0], w, h0, acc[g][0]);
                    FMA2(acc[g][1], w, h1, acc[g][1]);
                }
            }
            __syncthreads();
        }
    }
    int j = jBase + tx;
#pragma unroll
    for (int p = 0; p < 2; p++) {
        float i0,i1,f0,f1,g0,g1,o0,o1;
        upk(acc[0][p], i0, i1);
        upk(acc[1][p], f0, f1);
        upk(acc[2][p], g0, g1);
        upk(acc[3][p], o0, o1);
#pragma unroll
        for (int h2 = 0; h2 < 2; h2++) {
            int b = bBase + ty*4 + 2*p + h2;
            float gi = h2 ? i1 : i0;
            float gf = h2 ? f1 : f0;
            float gg = h2 ? g1 : g0;
            float go = h2 ? o1 : o0;
            if (pre) {
                const float* pr = pre + (size_t)b*4*HID;
                gi += pr[j]; gf += pr[HID + j];
                gg += pr[2*HID + j]; go += pr[3*HID + j];
            }
            if (bias) {
                gi += bias[j]; gf += bias[HID + j];
                gg += bias[2*HID + j]; go += bias[3*HID + j];
            }
            float cprev = firstC ? 0.f : c[(size_t)b*HID + j];
            float cn = sgf(gf)*cprev + sgf(gi)*tanh_acc(gg);
            c[(size_t)b*HID + j] = cn;
            hout[(size_t)b*hStride + j] = sgf(go)*tanh_acc(cn);
        }
    }
}

// ---- attention for one batch row (256 threads) ----
__device__ __forceinline__ void dev_attn(int b,
    const float* __restrict__ encproj, const float* __restrict__ encout,
    const float* __restrict__ q, const float* __restrict__ w2,
    const int* __restrict__ src, const int* __restrict__ tgt,
    const float* __restrict__ dec_embed,
    float* __restrict__ rin, float* __restrict__ attn_out, int t, float* sm)
{
    float* sq = sm;
    float* sa = sm + CH;
    int tid = threadIdx.x;
    for (int h = tid; h < CH; h += 256) sq[h] = q[(size_t)b*CH + h];
    __syncthreads();

    int warp = tid>>5, lane = tid&31;
    for (int s = warp; s < CS; s += 8) {
        const float* ep = encproj + ((size_t)b*CS + s)*CH;
        float part = 0.f;
#pragma unroll
        for (int i = 0; i < 8; i++) {
            int h = i*128 + lane*4;
            float4 e4 = *(const float4*)(ep + h);
            float4 w4 = *(const float4*)(w2 + h);
            part = fmaf(tanh_acc(e4.x + sq[h]),   w4.x, part);
            part = fmaf(tanh_acc(e4.y + sq[h+1]), w4.y, part);
            part = fmaf(tanh_acc(e4.z + sq[h+2]), w4.z, part);
            part = fmaf(tanh_acc(e4.w + sq[h+3]), w4.w, part);
        }
#pragma unroll
        for (int o = 16; o; o >>= 1) part += __shfl_xor_sync(0xffffffffu, part, o);
        if (lane == 0) sa[s] = part;
    }
    __syncthreads();

    if (warp == 0) {
        const int* sr = src + b*CS;
        float e[4];
#pragma unroll
        for (int i = 0; i < 4; i++)
            e[i] = (sr[lane + 32*i] != 0) ? sa[lane + 32*i] : -1e30f;
        float m = fmaxf(fmaxf(e[0], e[1]), fmaxf(e[2], e[3]));
#pragma unroll
        for (int o = 16; o; o >>= 1) m = fmaxf(m, __shfl_xor_sync(0xffffffffu, m, o));
        float p[4], ssum = 0.f;
#pragma unroll
        for (int i = 0; i < 4; i++){ p[i] = __expf(e[i]-m); ssum += p[i]; }
#pragma unroll
        for (int o = 16; o; o >>= 1) ssum += __shfl_xor_sync(0xffffffffu, ssum, o);
        float inv = __fdividef(1.f, ssum);
        float* ao = attn_out + ((size_t)b*(CT-1) + t)*CS;
#pragma unroll
        for (int i = 0; i < 4; i++){ float v = p[i]*inv; sa[lane+32*i] = v; ao[lane+32*i] = v; }
    }
    __syncthreads();

    {
        int h = tid*4;
        float4 cx = make_float4(0.f,0.f,0.f,0.f);
        const float* eo = encout + (size_t)b*CS*CH + h;
#pragma unroll 4
        for (int s = 0; s < CS; s++) {
            float a = sa[s];
            float4 v = *(const float4*)(eo + (size_t)s*CH);
            cx.x = fmaf(a, v.x, cx.x); cx.y = fmaf(a, v.y, cx.y);
            cx.z = fmaf(a, v.z, cx.z); cx.w = fmaf(a, v.w, cx.w);
        }
        *(float4*)(rin + (size_t)b*(CE+CH) + CE + h) = cx;
    }
    if (tid < CE/4) {
        int tok = tgt[b*CT + t];
        *(float4*)(rin + (size_t)b*(CE+CH) + tid*4) =
            *(const float4*)(dec_embed + (size_t)tok*CE + tid*4);
    }
    __syncthreads();
}

// ---------------- standalone kernels ----------------
__global__ void embed_enc(const int* __restrict__ src, const float* __restrict__ emb,
                          float* __restrict__ xemb)
{
    int i4 = blockIdx.x*blockDim.x + threadIdx.x;
    if (i4 >= MK*(CE/4)) return;
    int row = i4/(CE/4), q = i4%(CE/4);
    int t = row/CB, b = row%CB;
    int tok = src[b*CS + t];
    *(float4*)(xemb + (size_t)row*CE + 4*q) =
        *(const float4*)(emb + (size_t)tok*CE + 4*q);
}

__global__ __launch_bounds__(256)
void gemm_b_k(const float* A, int lda, const float* W, int ldb, int K,
              const float* bias, float* C, long long ldc)
{
    __shared__ __align__(16) float sm[2*KC*33*2 + KC*34];
    gemm_core(A, lda, W, ldb, K, bias, C, ldc,
              (int)blockIdx.y*32, (int)blockIdx.x*64, (float2*)sm, sm + 2*KC*33*2);
}

__global__ void init_dec(const float* __restrict__ x1, const float* __restrict__ encout,
                         const float* __restrict__ c0f, const float* __restrict__ c0b,
                         const float* __restrict__ c1f, const float* __restrict__ c1b,
                         float* __restrict__ dh0, float* __restrict__ dc0,
                         float* __restrict__ dh1, float* __restrict__ dc1)
{
    int idx = blockIdx.x*blockDim.x + threadIdx.x;
    if (idx >= CB*CH) return;
    int b = idx/CH, j = idx%CH;
    float h0, h1, cc0, cc1;
    if (j < CHD) {
        h0 = x1[((size_t)(CS-1)*CB + b)*CH + j];
        h1 = encout[((size_t)b*CS + CS-1)*CH + j];
        cc0 = c0f[(size_t)b*CHD + j];
        cc1 = c1f[(size_t)b*CHD + j];
    } else {
        h0 = x1[(size_t)b*CH + j];
        h1 = encout[(size_t)b*CS*CH + j];
        cc0 = c0b[(size_t)b*CHD + j - CHD];
        cc1 = c1b[(size_t)b*CHD + j - CHD];
    }
    dh0[idx] = h0; dc0[idx] = cc0;
    dh1[idx] = h1; dc1[idx] = cc1;
}

__global__ void zero_row0(float* __restrict__ out)
{
    int idx = blockIdx.x*blockDim.x + threadIdx.x;
    if (idx >= CB*CV) return;
    out[(size_t)(idx/CV)*CT*CV + idx%CV] = 0.f;
}

// ---------------- persistent encoder scan ----------------
__global__ __launch_bounds__(256, 2)
void enc_scan(const float* preA, const float* preB,
              const float* whhF, const float* whhB,
              float* cF, float* cB,
              float* hbase, long long tStride, long long hStride)
{
    __shared__ __align__(16) float sm[4*KC*33*2 + KC*34];
    float2* smw = (float2*)sm;
    float*  smh = sm + 4*KC*33*2;
    for (int s = 0; s < CS; s++) {
        int tf = s, tb = CS-1-s;
        for (int u = blockIdx.x; u < 256; u += gridDim.x) {
            int dir = u >> 7, jt = (u >> 3) & 15, bt = u & 7;
            int tt = dir ? tb : tf;
            const float* pre = dir ? preB + (size_t)tb*CB*2048 : preA + (size_t)tf*CB*2048;
            const float* whh = dir ? whhB : whhF;
            const float* hprev = nullptr;
            if (s) { int tp = dir ? tb+1 : tf-1;
                     hprev = hbase + (size_t)tp*tStride + (dir ? CHD : 0); }
            float* c    = dir ? cB : cF;
            float* hout = hbase + (size_t)tt*tStride + (dir ? CHD : 0);
            cell_core(hprev, (int)hStride, CHD, whh,
                      nullptr, 0, 0, nullptr,
                      pre, nullptr, CHD,
                      c, hout, hStride, jt*32, bt*32, s == 0, smw, smh);
        }
        gbar();
    }
}

// ---------------- persistent decoder loop ----------------
__global__ __launch_bounds__(256, 2)
void dec_loop(const float* encproj, const float* encout,
              const float* attn_w1, const float* attn_b1, const float* attn_w2,
              const int* src, const int* tgt, const float* dec_embed,
              const float* dl0_wih, const float* dl0_whh, const float* dl0_b,
              const float* dl1_wih, const float* dl1_whh, const float* dl1_b,
              const float* fc_w, const float* fc_b,
              float* dh0, float* dc0, float* dh1, float* dc1,
              float* qb, float* rin, float* out, float* attn_out)
{
    __shared__ __align__(16) float sm[4*KC*33*2 + KC*34];
    float2* smw = (float2*)sm;
    float*  smh = sm + 4*KC*33*2;
    unsigned nb = gridDim.x;

    // initial q = h1 @ w1_q^T + b1 (128 tiles)
    for (int u = blockIdx.x; u < 128; u += nb)
        gemm_core(dh1, CH, attn_w1 + CH, 2*CH, CH, attn_b1, qb, CH,
                  (u >> 4)*32, (u & 15)*64, smw, smh);
    gbar();

    for (int t = 0; t < CT-1; t++) {
        int cur = t & 1, nxt = 1 - cur;
        float* h0c = dh0 + (size_t)cur*CB*CH; float* h0n = dh0 + (size_t)nxt*CB*CH;
        float* h1c = dh1 + (size_t)cur*CB*CH; float* h1n = dh1 + (size_t)nxt*CB*CH;

        // B: attention (256 rows)
        for (int u = blockIdx.x; u < CB; u += nb)
            dev_attn(u, encproj, encout, qb, attn_w2, src, tgt, dec_embed,
                     rin, attn_out, t, sm);
        gbar();

        // C: fused cell0: gates = rin@wih0 + h0c@whh0 + b0 (256 tiles)
        for (int u = blockIdx.x; u < 256; u += nb)
            cell_core(rin, CE+CH, CE+CH, dl0_wih,
                      h0c, CH, CH, dl0_whh,
                      nullptr, dl0_b, CH,
                      dc0, h0n, CH, (u >> 3)*32, (u & 7)*32, false, smw, smh);
        gbar();

        // E: fused cell1: gates = h0n@wih1 + h1c@whh1 + b1 (256 tiles)
        for (int u = blockIdx.x; u < 256; u += nb)
            cell_core(h0n, CH, CH, dl1_wih,
                      h1c, CH, CH, dl1_whh,
                      nullptr, dl1_b, CH,
                      dc1, h1n, CH, (u >> 3)*32, (u & 7)*32, false, smw, smh);
        gbar();

        // G: logits (32 tiles) + next q (128 tiles)
        for (int u = blockIdx.x; u < 160; u += nb) {
            if (u < 32)
                gemm_core(h1n, CH, fc_w, CH, CH, fc_b,
                          out + (size_t)(t+1)*CV, (long long)CT*CV,
                          (u >> 2)*32, (u & 3)*64, smw, smh);
            else {
                int v = u - 32;
                gemm_core(h1n, CH, attn_w1 + CH, 2*CH, CH, attn_b1, qb, CH,
                          (v >> 4)*32, (v & 15)*64, smw, smh);
            }
        }
        gbar();
    }
}

extern "C" void kernel_launch(void* const* d_in, const int* in_sizes, int n_in,
                              void* d_out, int out_size)
{
    const int*   src       = (const int*)  d_in[0];
    const int*   tgt       = (const int*)  d_in[1];
    const float* enc_embed = (const float*)d_in[2];
    const float* dec_embed = (const float*)d_in[3];
    const float* l0f_wih=(const float*)d_in[4],  *l0f_whh=(const float*)d_in[5],  *l0f_b=(const float*)d_in[6];
    const float* l0b_wih=(const float*)d_in[7],  *l0b_whh=(const float*)d_in[8],  *l0b_b=(const float*)d_in[9];
    const float* l1f_wih=(const float*)d_in[10], *l1f_whh=(const float*)d_in[11], *l1f_b=(const float*)d_in[12];
    const float* l1b_wih=(const float*)d_in[13], *l1b_whh=(const float*)d_in[14], *l1b_b=(const float*)d_in[15];
    const float* dl0_wih=(const float*)d_in[16], *dl0_whh=(const float*)d_in[17], *dl0_b=(const float*)d_in[18];
    const float* dl1_wih=(const float*)d_in[19], *dl1_whh=(const float*)d_in[20], *dl1_b=(const float*)d_in[21];
    const float* attn_w1=(const float*)d_in[22], *attn_b1=(const float*)d_in[23];
    const float* attn_w2=(const float*)d_in[24];
    const float* fc_w=(const float*)d_in[26],    *fc_b=(const float*)d_in[27];
    float* out = (float*)d_out;

    float* S;
    cudaGetSymbolAddress((void**)&S, g_s);
    float* xemb = S+OFF_XEMB;  float* preA = S+OFF_PREA;  float* preB = S+OFF_PREB;
    float* x1 = S+OFF_X1;      float* encout = S+OFF_ENCOUT; float* encproj = S+OFF_ENCPROJ;
    float* c0f = S+OFF_C0F;    float* c0b = S+OFF_C0B;
    float* c1f = S+OFF_C1F;    float* c1b = S+OFF_C1B;
    float* dh0 = S+OFF_DH0;    float* dc0 = S+OFF_DC0;
    float* dh1 = S+OFF_DH1;    float* dc1 = S+OFF_DC1;
    float* qb = S+OFF_Q;       float* rin = S+OFF_RIN;
    float* attn_out = out + (size_t)CB*CT*CV;

    int dev = 0; cudaGetDevice(&dev);
    int sms = 0; cudaDeviceGetAttribute(&sms, cudaDevAttrMultiProcessorCount, dev);
    int occE = 1, occD = 1;
    cudaOccupancyMaxActiveBlocksPerMultiprocessor(&occE, enc_scan, 256, 0);
    cudaOccupancyMaxActiveBlocksPerMultiprocessor(&occD, dec_loop, 256, 0);
    if (occE < 1) occE = 1;
    if (occD < 1) occD = 1;
    unsigned nbE = (unsigned)(sms * occE);
    unsigned nbD = (unsigned)(sms * occD);

    embed_enc<<<(MK*(CE/4)+255)/256, 256>>>(src, enc_embed, xemb);

    // encoder layer0 pre-projections
    gemm_b_k<<<dim3(2048/64, MK/32), 256>>>(xemb, CE, l0f_wih, CE, CE, l0f_b, preA, 2048);
    gemm_b_k<<<dim3(2048/64, MK/32), 256>>>(xemb, CE, l0b_wih, CE, CE, l0b_b, preB, 2048);
    enc_scan<<<nbE, 256>>>(preA, preB, l0f_whh, l0b_whh, c0f, c0b,
                           x1, (long long)CB*CH, (long long)CH);
    // encoder layer1 pre-projections
    gemm_b_k<<<dim3(2048/64, MK/32), 256>>>(x1, CH, l1f_wih, CH, CH, l1f_b, preA, 2048);
    gemm_b_k<<<dim3(2048/64, MK/32), 256>>>(x1, CH, l1b_wih, CH, CH, l1b_b, preB, 2048);
    enc_scan<<<nbE, 256>>>(preA, preB, l1f_whh, l1b_whh, c1f, c1b,
                           encout, (long long)CH, (long long)CS*CH);

    init_dec<<<(CB*CH+255)/256, 256>>>(x1, encout, c0f, c0b, c1f, c1b, dh0, dc0, dh1, dc1);
    // enc_proj = encout @ w1_enc^T
    gemm_b_k<<<dim3(CH/64, MK/32), 256>>>(encout, CH, attn_w1, 2*CH, CH, nullptr, encproj, CH);
    zero_row0<<<(CB*CV+255)/256, 256>>>(out);

    dec_loop<<<nbD, 256>>>(encproj, encout, attn_w1, attn_b1, attn_w2,
                           src, tgt, dec_embed,
                           dl0_wih, dl0_whh, dl0_b, dl1_wih, dl1_whh, dl1_b,
                           fc_w, fc_b, dh0, dc0, dh1, dc1,
                           qb, rin, out, attn_out);
}

// round 11
// speedup vs baseline: 1.5583x; 1.5583x over previous
#include <cuda_runtime.h>
#include <cstddef>
typedef unsigned long long ull;

#define CB 256
#define CS 128
#define CT 128
#define CE 512
#define CH 1024
#define CHD 512
#define CV 256
#define MK (CS*CB)

#define OFF_XEMB   ((size_t)0)
#define OFF_PREA   (OFF_XEMB + (size_t)MK*CE)
#define OFF_PREB   (OFF_PREA + (size_t)MK*2048)
#define OFF_X1     (OFF_PREB + (size_t)MK*2048)
#define OFF_ENCOUT (OFF_X1 + (size_t)MK*CH)
#define OFF_ENCPROJ (OFF_ENCOUT + (size_t)MK*CH)
#define OFF_C0F    (OFF_ENCPROJ + (size_t)MK*CH)
#define OFF_C0B    (OFF_C0F + (size_t)CB*CHD)
#define OFF_C1F    (OFF_C0B + (size_t)CB*CHD)
#define OFF_C1B    (OFF_C1F + (size_t)CB*CHD)
#define OFF_DH0    (OFF_C1B + (size_t)CB*CHD)
#define OFF_DC0    (OFF_DH0 + (size_t)2*CB*CH)
#define OFF_DH1    (OFF_DC0 + (size_t)CB*CH)
#define OFF_DC1    (OFF_DH1 + (size_t)2*CB*CH)
#define OFF_Q      (OFF_DC1 + (size_t)CB*CH)
#define OFF_RIN    (OFF_Q + (size_t)CB*CH)
#define OFF_P0     (OFF_RIN + (size_t)CB*(CE+CH))
#define OFF_P1     (OFF_P0 + (size_t)8*CB*CH)
#define SCRATCH_FLOATS (OFF_P1 + (size_t)8*CB*CH)

__device__ float g_s[SCRATCH_FLOATS];
__device__ unsigned g_cnt;
__device__ unsigned g_gen;

#define FMA2(d,a,b,c) asm("fma.rn.f32x2 %0, %1, %2, %3;" : "=l"(d) : "l"(a), "l"(b), "l"(c))
__device__ __forceinline__ void upk(ull v, float& lo, float& hi){
    asm("mov.b64 {%0,%1}, %2;" : "=f"(lo), "=f"(hi) : "l"(v));
}
__device__ __forceinline__ float tanh_acc(float x){
    float xc = fminf(fmaxf(x, -7.90531110763549805f), 7.90531110763549805f);
    float x2 = xc*xc;
    float p = fmaf(x2, -2.76076847742355e-16f, 2.00018790482477e-13f);
    p = fmaf(x2, p, -8.60467152213735e-11f);
    p = fmaf(x2, p, 5.12229709037114e-08f);
    p = fmaf(x2, p, 1.48572235717979e-05f);
    p = fmaf(x2, p, 6.37261928875436e-04f);
    p = fmaf(x2, p, 4.89352455891786e-03f);
    p = p*xc;
    float q = fmaf(x2, 1.19825839466702e-06f, 1.18534705686654e-04f);
    q = fmaf(x2, q, 2.26843463243900e-03f);
    q = fmaf(x2, q, 4.89352518554385e-03f);
    return __fdividef(p, q);
}
__device__ __forceinline__ float sgf(float x){
    return __fdividef(1.f, 1.f + __expf(-x));
}

__device__ __forceinline__ void gbar()
{
    __syncthreads();
    if (threadIdx.x == 0) {
        __threadfence();
        unsigned gen = atomicAdd(&g_gen, 0u);
        if (atomicAdd(&g_cnt, 1u) == gridDim.x - 1u) {
            atomicExch(&g_cnt, 0u);
            __threadfence();
            atomicAdd(&g_gen, 1u);
        } else {
            while (atomicAdd(&g_gen, 0u) == gen) __nanosleep(256);
        }
        __threadfence();
    }
    __syncthreads();
}

// ===== k-packed GEMM: C[64m x 64n] = A.W^T + bias; 256 thr, warp owns 8 m =====
__device__ __forceinline__ void gemm2(const float* __restrict__ A, int lda,
    const float* __restrict__ W, int ldb, int K, const float* __restrict__ bias,
    float* __restrict__ C, long long ldc, int mBase, int nBase, float* sb)
{
    float2 (*swg)[16][33] = (float2(*)[16][33])sb;       // 2112 floats
    float2 (*sha)[65]     = (float2(*)[65])(sb + 2112);  // 2080 floats
    int tid = threadIdx.x, lane = tid & 31, wid = tid >> 5;
    ull acc[2][8] = {};
    for (int k0 = 0; k0 < K; k0 += 32) {
        int f = tid;
#pragma unroll
        for (int i = 0; i < 2; i++) {
            int r = f >> 3, q = f & 7, s = r >> 5, j = r & 31;
            float4 v = *(const float4*)(W + (size_t)(nBase + s*32 + j)*ldb + k0 + 4*q);
            swg[s][2*q][j]   = make_float2(v.x, v.y);
            swg[s][2*q+1][j] = make_float2(v.z, v.w);
            f += 256;
        }
        f = tid;
#pragma unroll
        for (int i = 0; i < 2; i++) {
            int r = f >> 3, q = f & 7;
            float4 v = *(const float4*)(A + (size_t)(mBase + r)*lda + k0 + 4*q);
            sha[2*q][r]   = make_float2(v.x, v.y);
            sha[2*q+1][r] = make_float2(v.z, v.w);
            f += 256;
        }
        __syncthreads();
#pragma unroll
        for (int kk = 0; kk < 16; kk++) {
            ull w0 = *(ull*)&swg[0][kk][lane];
            ull w1 = *(ull*)&swg[1][kk][lane];
#pragma unroll
            for (int m = 0; m < 8; m++) {
                ull h = *(ull*)&sha[kk][wid*8 + m];
                FMA2(acc[0][m], w0, h, acc[0][m]);
                FMA2(acc[1][m], w1, h, acc[1][m]);
            }
        }
        __syncthreads();
    }
#pragma unroll
    for (int s = 0; s < 2; s++) {
        int n = nBase + s*32 + lane;
        float bz = bias ? bias[n] : 0.f;
#pragma unroll
        for (int m = 0; m < 8; m++) {
            float lo, hi; upk(acc[s][m], lo, hi);
            C[(long long)(mBase + wid*8 + m)*ldc + n] = lo + hi + bz;
        }
    }
}

// ===== gate partial GEMM: P[g][64b][32j] += A[64b][K] . W4[4*CH rows][K]^T =====
__device__ __forceinline__ void gate_gemm(const float* __restrict__ A, int lda, int K,
    const float* __restrict__ W, float* __restrict__ P, int jt, int bt, float* sb)
{
    float2 (*swc)[16][33] = (float2(*)[16][33])sb;       // 4224 floats
    float2 (*sha)[65]     = (float2(*)[65])(sb + 4224);  // 2080 floats
    int tid = threadIdx.x, lane = tid & 31, wid = tid >> 5;
    int jBase = jt*32, bBase = bt*64;
    ull acc[4][8] = {};
    for (int k0 = 0; k0 < K; k0 += 32) {
        int f = tid;
#pragma unroll
        for (int i = 0; i < 4; i++) {
            int r = f >> 3, q = f & 7, g = r >> 5, j = r & 31;
            float4 v = *(const float4*)(W + (size_t)(g*CH + jBase + j)*K + k0 + 4*q);
            swc[g][2*q][j]   = make_float2(v.x, v.y);
            swc[g][2*q+1][j] = make_float2(v.z, v.w);
            f += 256;
        }
        f = tid;
#pragma unroll
        for (int i = 0; i < 2; i++) {
            int r = f >> 3, q = f & 7;
            float4 v = *(const float4*)(A + (size_t)(bBase + r)*lda + k0 + 4*q);
            sha[2*q][r]   = make_float2(v.x, v.y);
            sha[2*q+1][r] = make_float2(v.z, v.w);
            f += 256;
        }
        __syncthreads();
#pragma unroll
        for (int kk = 0; kk < 16; kk++) {
            ull w0 = *(ull*)&swc[0][kk][lane];
            ull w1 = *(ull*)&swc[1][kk][lane];
            ull w2 = *(ull*)&swc[2][kk][lane];
            ull w3 = *(ull*)&swc[3][kk][lane];
#pragma unroll
            for (int m = 0; m < 8; m++) {
                ull h = *(ull*)&sha[kk][wid*8 + m];
                FMA2(acc[0][m], w0, h, acc[0][m]);
                FMA2(acc[1][m], w1, h, acc[1][m]);
                FMA2(acc[2][m], w2, h, acc[2][m]);
                FMA2(acc[3][m], w3, h, acc[3][m]);
            }
        }
        __syncthreads();
    }
    int j = jBase + lane;
#pragma unroll
    for (int g = 0; g < 4; g++)
#pragma unroll
        for (int m = 0; m < 8; m++) {
            float lo, hi; upk(acc[g][m], lo, hi);
            int b = bBase + wid*8 + m;
            P[(size_t)(g*CB + b)*CH + j] = lo + hi;
        }
}

// ===== cell finish: gates = P(seg0)+P(seg1)+bias -> c,h =====
__device__ __forceinline__ void cell_finish(const float* __restrict__ P,
    const float* __restrict__ bias, float* __restrict__ c, float* __restrict__ hout, int idx)
{
    int j2 = (idx & 511)*2, b = idx >> 9;
    float2 gs[4];
#pragma unroll
    for (int g = 0; g < 4; g++) {
        float2 s = *(const float2*)(bias + g*CH + j2);
        float2 p0 = *(const float2*)(P + (size_t)(g*CB + b)*CH + j2);
        float2 p1 = *(const float2*)(P + (size_t)((4+g)*CB + b)*CH + j2);
        gs[g] = make_float2(s.x + p0.x + p1.x, s.y + p0.y + p1.y);
    }
    float2 cc = *(const float2*)(c + (size_t)b*CH + j2);
    float cnx = sgf(gs[1].x)*cc.x + sgf(gs[0].x)*tanh_acc(gs[2].x);
    float cny = sgf(gs[1].y)*cc.y + sgf(gs[0].y)*tanh_acc(gs[2].y);
    *(float2*)(c + (size_t)b*CH + j2) = make_float2(cnx, cny);
    *(float2*)(hout + (size_t)b*CH + j2) =
        make_float2(sgf(gs[3].x)*tanh_acc(cnx), sgf(gs[3].y)*tanh_acc(cny));
}

// ===== encoder cell (direct): gates = pre + hprev.whh^T; 32j x 64b; HID=CHD =====
__device__ __forceinline__ void cell_enc(const float* __restrict__ hprev, long long lda,
    const float* __restrict__ whh, const float* __restrict__ pre,
    float* __restrict__ c, float* __restrict__ hout, long long hStride,
    int jt, int bt, bool first, float* sb)
{
    float2 (*swc)[16][33] = (float2(*)[16][33])sb;
    float2 (*sha)[65]     = (float2(*)[65])(sb + 4224);
    int tid = threadIdx.x, lane = tid & 31, wid = tid >> 5;
    int jBase = jt*32, bBase = bt*64;
    ull acc[4][8] = {};
    if (!first) {
        for (int k0 = 0; k0 < CHD; k0 += 32) {
            int f = tid;
#pragma unroll
            for (int i = 0; i < 4; i++) {
                int r = f >> 3, q = f & 7, g = r >> 5, j = r & 31;
                float4 v = *(const float4*)(whh + (size_t)(g*CHD + jBase + j)*CHD + k0 + 4*q);
                swc[g][2*q][j]   = make_float2(v.x, v.y);
                swc[g][2*q+1][j] = make_float2(v.z, v.w);
                f += 256;
            }
            f = tid;
#pragma unroll
            for (int i = 0; i < 2; i++) {
                int r = f >> 3, q = f & 7;
                float4 v = *(const float4*)(hprev + (size_t)(bBase + r)*lda + k0 + 4*q);
                sha[2*q][r]   = make_float2(v.x, v.y);
                sha[2*q+1][r] = make_float2(v.z, v.w);
                f += 256;
            }
            __syncthreads();
#pragma unroll
            for (int kk = 0; kk < 16; kk++) {
                ull w0 = *(ull*)&swc[0][kk][lane];
                ull w1 = *(ull*)&swc[1][kk][lane];
                ull w2 = *(ull*)&swc[2][kk][lane];
                ull w3 = *(ull*)&swc[3][kk][lane];
#pragma unroll
                for (int m = 0; m < 8; m++) {
                    ull h = *(ull*)&sha[kk][wid*8 + m];
                    FMA2(acc[0][m], w0, h, acc[0][m]);
                    FMA2(acc[1][m], w1, h, acc[1][m]);
                    FMA2(acc[2][m], w2, h, acc[2][m]);
                    FMA2(acc[3][m], w3, h, acc[3][m]);
                }
            }
            __syncthreads();
        }
    }
    int j = jBase + lane;
#pragma unroll
    for (int m = 0; m < 8; m++) {
        int b = bBase + wid*8 + m;
        const float* pr = pre + (size_t)b*2048;
        float gv[4];
#pragma unroll
        for (int g = 0; g < 4; g++) {
            float lo, hi; upk(acc[g][m], lo, hi);
            gv[g] = lo + hi + pr[g*CHD + j];
        }
        float cp = first ? 0.f : c[(size_t)b*CHD + j];
        float cn = sgf(gv[1])*cp + sgf(gv[0])*tanh_acc(gv[2]);
        c[(size_t)b*CHD + j] = cn;
        hout[(size_t)b*hStride + j] = sgf(gv[3])*tanh_acc(cn);
    }
}

// ===== attention for one batch row =====
__device__ __forceinline__ void dev_attn(int b,
    const float* __restrict__ encproj, const float* __restrict__ encout,
    const float* __restrict__ q, const float* __restrict__ w2,
    const int* __restrict__ src, const int* __restrict__ tgt,
    const float* __restrict__ dec_embed,
    float* __restrict__ rin, float* __restrict__ attn_out, int t, float* sm)
{
    float* sq = sm;
    float* sa = sm + CH;
    int tid = threadIdx.x;
    for (int h = tid; h < CH; h += 256) sq[h] = q[(size_t)b*CH + h];
    __syncthreads();

    int warp = tid >> 5, lane = tid & 31;
    for (int s = warp; s < CS; s += 8) {
        const float* ep = encproj + ((size_t)b*CS + s)*CH;
        float part = 0.f;
#pragma unroll
        for (int i = 0; i < 8; i++) {
            int h = i*128 + lane*4;
            float4 e4 = *(const float4*)(ep + h);
            float4 w4 = *(const float4*)(w2 + h);
            part = fmaf(tanh_acc(e4.x + sq[h]),   w4.x, part);
            part = fmaf(tanh_acc(e4.y + sq[h+1]), w4.y, part);
            part = fmaf(tanh_acc(e4.z + sq[h+2]), w4.z, part);
            part = fmaf(tanh_acc(e4.w + sq[h+3]), w4.w, part);
        }
#pragma unroll
        for (int o = 16; o; o >>= 1) part += __shfl_xor_sync(0xffffffffu, part, o);
        if (lane == 0) sa[s] = part;
    }
    __syncthreads();

    if (warp == 0) {
        const int* sr = src + b*CS;
        float e[4];
#pragma unroll
        for (int i = 0; i < 4; i++)
            e[i] = (sr[lane + 32*i] != 0) ? sa[lane + 32*i] : -1e30f;
        float m = fmaxf(fmaxf(e[0], e[1]), fmaxf(e[2], e[3]));
#pragma unroll
        for (int o = 16; o; o >>= 1) m = fmaxf(m, __shfl_xor_sync(0xffffffffu, m, o));
        float p[4], ssum = 0.f;
#pragma unroll
        for (int i = 0; i < 4; i++){ p[i] = __expf(e[i]-m); ssum += p[i]; }
#pragma unroll
        for (int o = 16; o; o >>= 1) ssum += __shfl_xor_sync(0xffffffffu, ssum, o);
        float inv = __fdividef(1.f, ssum);
        float* ao = attn_out + ((size_t)b*(CT-1) + t)*CS;
#pragma unroll
        for (int i = 0; i < 4; i++){ float v = p[i]*inv; sa[lane+32*i] = v; ao[lane+32*i] = v; }
    }
    __syncthreads();

    {
        int h = tid*4;
        float4 cx = make_float4(0.f, 0.f, 0.f, 0.f);
        const float* eo = encout + (size_t)b*CS*CH + h;
#pragma unroll 4
        for (int s = 0; s < CS; s++) {
            float a = sa[s];
            float4 v = *(const float4*)(eo + (size_t)s*CH);
            cx.x = fmaf(a, v.x, cx.x); cx.y = fmaf(a, v.y, cx.y);
            cx.z = fmaf(a, v.z, cx.z); cx.w = fmaf(a, v.w, cx.w);
        }
        *(float4*)(rin + (size_t)b*(CE+CH) + CE + h) = cx;
    }
    if (tid < CE/4) {
        int tok = tgt[b*CT + t];
        *(float4*)(rin + (size_t)b*(CE+CH) + tid*4) =
            *(const float4*)(dec_embed + (size_t)tok*CE + tid*4);
    }
    __syncthreads();
}

// ===== standalone kernels =====
__global__ void embed_enc(const int* __restrict__ src, const float* __restrict__ emb,
                          float* __restrict__ xemb)
{
    int i4 = blockIdx.x*blockDim.x + threadIdx.x;
    if (i4 >= MK*(CE/4)) return;
    int row = i4/(CE/4), q = i4%(CE/4);
    int t = row/CB, b = row%CB;
    int tok = src[b*CS + t];
    *(float4*)(xemb + (size_t)row*CE + 4*q) =
        *(const float4*)(emb + (size_t)tok*CE + 4*q);
}

__global__ __launch_bounds__(256, 2)
void gemm_k2(const float* A, int lda, const float* W, int ldb, int K,
             const float* bias, float* C, long long ldc)
{
    __shared__ __align__(16) float sb[4192];
    gemm2(A, lda, W, ldb, K, bias, C, ldc, (int)blockIdx.y*64, (int)blockIdx.x*64, sb);
}

__global__ void init_dec(const float* __restrict__ x1, const float* __restrict__ encout,
                         const float* __restrict__ c0f, const float* __restrict__ c0b,
                         const float* __restrict__ c1f, const float* __restrict__ c1b,
                         float* __restrict__ dh0, float* __restrict__ dc0,
                         float* __restrict__ dh1, float* __restrict__ dc1)
{
    int idx = blockIdx.x*blockDim.x + threadIdx.x;
    if (idx >= CB*CH) return;
    int b = idx/CH, j = idx%CH;
    float h0, h1, cc0, cc1;
    if (j < CHD) {
        h0 = x1[((size_t)(CS-1)*CB + b)*CH + j];
        h1 = encout[((size_t)b*CS + CS-1)*CH + j];
        cc0 = c0f[(size_t)b*CHD + j];
        cc1 = c1f[(size_t)b*CHD + j];
    } else {
        h0 = x1[(size_t)b*CH + j];
        h1 = encout[(size_t)b*CS*CH + j];
        cc0 = c0b[(size_t)b*CHD + j - CHD];
        cc1 = c1b[(size_t)b*CHD + j - CHD];
    }
    dh0[idx] = h0; dc0[idx] = cc0;
    dh1[idx] = h1; dc1[idx] = cc1;
}

__global__ void zero_row0(float* __restrict__ out)
{
    int idx = blockIdx.x*blockDim.x + threadIdx.x;
    if (idx >= CB*CV) return;
    out[(size_t)(idx/CV)*CT*CV + idx%CV] = 0.f;
}

// ===== persistent encoder scan =====
__global__ __launch_bounds__(256, 2)
void enc_scan(const float* preA, const float* preB,
              const float* whhF, const float* whhB,
              float* cF, float* cB,
              float* hbase, long long tStride, long long hStride)
{
    __shared__ __align__(16) float sb[6304];
    for (int s = 0; s < CS; s++) {
        int tf = s, tb = CS-1-s;
        for (int u = blockIdx.x; u < 128; u += gridDim.x) {
            int dir = u >> 6, jt = (u >> 2) & 15, bt = u & 3;
            int tt = dir ? tb : tf;
            const float* pre = dir ? preB + (size_t)tb*CB*2048 : preA + (size_t)tf*CB*2048;
            const float* whh = dir ? whhB : whhF;
            const float* hprev = nullptr;
            if (s) { int tp = dir ? tb+1 : tf-1;
                     hprev = hbase + (size_t)tp*tStride + (dir ? CHD : 0); }
            float* c    = dir ? cB : cF;
            float* hout = hbase + (size_t)tt*tStride + (dir ? CHD : 0);
            cell_enc(hprev, hStride, whh, pre, c, hout, hStride, jt, bt, s == 0, sb);
        }
        gbar();
    }
}

// ===== persistent decoder loop =====
__global__ __launch_bounds__(256, 2)
void dec_loop(const float* encproj, const float* encout,
              const float* attn_w1, const float* attn_b1, const float* attn_w2,
              const int* src, const int* tgt, const float* dec_embed,
              const float* dl0_wih, const float* dl0_whh, const float* dl0_b,
              const float* dl1_wih, const float* dl1_whh, const float* dl1_b,
              const float* fc_w, const float* fc_b,
              float* dh0, float* dc0, float* dh1, float* dc1,
              float* qb, float* rin, float* P0, float* P1,
              float* out, float* attn_out)
{
    __shared__ __align__(16) float sb[6304];
    unsigned nb = gridDim.x;
    int tid = threadIdx.x;

    // q = h1 @ w1_q^T + b1 (4 m-tiles x 16 n-tiles)
    for (int u = blockIdx.x; u < 64; u += nb)
        gemm2(dh1, CH, attn_w1 + CH, 2*CH, CH, attn_b1, qb, CH,
              (u & 3)*64, (u >> 2)*64, sb);
    gbar();

    for (int t = 0; t < CT-1; t++) {
        int cur = t & 1, nxt = 1 - cur;
        float* h0c = dh0 + (size_t)cur*CB*CH; float* h0n = dh0 + (size_t)nxt*CB*CH;
        float* h1c = dh1 + (size_t)cur*CB*CH; float* h1n = dh1 + (size_t)nxt*CB*CH;

        // B: attention
        for (int u = blockIdx.x; u < CB; u += nb)
            dev_attn(u, encproj, encout, qb, attn_w2, src, tgt, dec_embed,
                     rin, attn_out, t, sb);
        gbar();

        // C: cell0 gate GEMMs (seg0: rin@wih, seg1: h0c@whh)
        for (int u = blockIdx.x; u < 256; u += nb) {
            int seg = u >> 7, jt = (u & 127) >> 2, bt = u & 3;
            if (seg == 0)
                gate_gemm(rin, CE+CH, CE+CH, dl0_wih, P0, jt, bt, sb);
            else
                gate_gemm(h0c, CH, CH, dl0_whh, P0 + (size_t)4*CB*CH, jt, bt, sb);
        }
        gbar();

        // D: cell0 finish
        for (int idx = blockIdx.x*256 + tid; idx < CB*CH/2; idx += nb*256)
            cell_finish(P0, dl0_b, dc0, h0n, idx);
        gbar();

        // E: cell1 gate GEMMs (seg0: h0n@wih, seg1: h1c@whh)
        for (int u = blockIdx.x; u < 256; u += nb) {
            int seg = u >> 7, jt = (u & 127) >> 2, bt = u & 3;
            if (seg == 0)
                gate_gemm(h0n, CH, CH, dl1_wih, P1, jt, bt, sb);
            else
                gate_gemm(h1c, CH, CH, dl1_whh, P1 + (size_t)4*CB*CH, jt, bt, sb);
        }
        gbar();

        // F: cell1 finish
        for (int idx = blockIdx.x*256 + tid; idx < CB*CH/2; idx += nb*256)
            cell_finish(P1, dl1_b, dc1, h1n, idx);
        gbar();

        // G: logits (16 tiles) + next q (64 tiles)
        for (int u = blockIdx.x; u < 80; u += nb) {
            if (u < 16)
                gemm2(h1n, CH, fc_w, CH, CH, fc_b,
                      out + (size_t)(t+1)*CV, (long long)CT*CV,
                      (u & 3)*64, (u >> 2)*64, sb);
            else {
                int v = u - 16;
                gemm2(h1n, CH, attn_w1 + CH, 2*CH, CH, attn_b1, qb, CH,
                      (v & 3)*64, (v >> 2)*64, sb);
            }
        }
        gbar();
    }
}

extern "C" void kernel_launch(void* const* d_in, const int* in_sizes, int n_in,
                              void* d_out, int out_size)
{
    const int*   src       = (const int*)  d_in[0];
    const int*   tgt       = (const int*)  d_in[1];
    const float* enc_embed = (const float*)d_in[2];
    const float* dec_embed = (const float*)d_in[3];
    const float* l0f_wih=(const float*)d_in[4],  *l0f_whh=(const float*)d_in[5],  *l0f_b=(const float*)d_in[6];
    const float* l0b_wih=(const float*)d_in[7],  *l0b_whh=(const float*)d_in[8],  *l0b_b=(const float*)d_in[9];
    const float* l1f_wih=(const float*)d_in[10], *l1f_whh=(const float*)d_in[11], *l1f_b=(const float*)d_in[12];
    const float* l1b_wih=(const float*)d_in[13], *l1b_whh=(const float*)d_in[14], *l1b_b=(const float*)d_in[15];
    const float* dl0_wih=(const float*)d_in[16], *dl0_whh=(const float*)d_in[17], *dl0_b=(const float*)d_in[18];
    const float* dl1_wih=(const float*)d_in[19], *dl1_whh=(const float*)d_in[20], *dl1_b=(const float*)d_in[21];
    const float* attn_w1=(const float*)d_in[22], *attn_b1=(const float*)d_in[23];
    const float* attn_w2=(const float*)d_in[24];
    const float* fc_w=(const float*)d_in[26],    *fc_b=(const float*)d_in[27];
    float* out = (float*)d_out;

    float* S;
    cudaGetSymbolAddress((void**)&S, g_s);
    float* xemb = S+OFF_XEMB;  float* preA = S+OFF_PREA;  float* preB = S+OFF_PREB;
    float* x1 = S+OFF_X1;      float* encout = S+OFF_ENCOUT; float* encproj = S+OFF_ENCPROJ;
    float* c0f = S+OFF_C0F;    float* c0b = S+OFF_C0B;
    float* c1f = S+OFF_C1F;    float* c1b = S+OFF_C1B;
    float* dh0 = S+OFF_DH0;    float* dc0 = S+OFF_DC0;
    float* dh1 = S+OFF_DH1;    float* dc1 = S+OFF_DC1;
    float* qb = S+OFF_Q;       float* rin = S+OFF_RIN;
    float* P0 = S+OFF_P0;      float* P1 = S+OFF_P1;
    float* attn_out = out + (size_t)CB*CT*CV;

    int dev = 0; cudaGetDevice(&dev);
    int sms = 0; cudaDeviceGetAttribute(&sms, cudaDevAttrMultiProcessorCount, dev);
    int occ = 1;
    cudaOccupancyMaxActiveBlocksPerMultiprocessor(&occ, dec_loop, 256, 0);
    if (occ < 1) occ = 1;
    unsigned nb = (unsigned)(sms * occ);

    embed_enc<<<(MK*(CE/4)+255)/256, 256>>>(src, enc_embed, xemb);

    // encoder layer0 pre-projections: [MK,512] @ [2048,512]^T
    gemm_k2<<<dim3(2048/64, MK/64), 256>>>(xemb, CE, l0f_wih, CE, CE, l0f_b, preA, 2048);
    gemm_k2<<<dim3(2048/64, MK/64), 256>>>(xemb, CE, l0b_wih, CE, CE, l0b_b, preB, 2048);
    enc_scan<<<nb, 256>>>(preA, preB, l0f_whh, l0b_whh, c0f, c0b,
                          x1, (long long)CB*CH, (long long)CH);
    // encoder layer1 pre-projections: [MK,1024] @ [2048,1024]^T
    gemm_k2<<<dim3(2048/64, MK/64), 256>>>(x1, CH, l1f_wih, CH, CH, l1f_b, preA, 2048);
    gemm_k2<<<dim3(2048/64, MK/64), 256>>>(x1, CH, l1b_wih, CH, CH, l1b_b, preB, 2048);
    enc_scan<<<nb, 256>>>(preA, preB, l1f_whh, l1b_whh, c1f, c1b,
                          encout, (long long)CH, (long long)CS*CH);

    init_dec<<<(CB*CH+255)/256, 256>>>(x1, encout, c0f, c0b, c1f, c1b, dh0, dc0, dh1, dc1);
    // enc_proj = encout @ w1_enc^T
    gemm_k2<<<dim3(CH/64, MK/64), 256>>>(encout, CH, attn_w1, 2*CH, CH, nullptr, encproj, CH);
    zero_row0<<<(CB*CV+255)/256, 256>>>(out);

    dec_loop<<<nb, 256>>>(encproj, encout, attn_w1, attn_b1, attn_w2,
                          src, tgt, dec_embed,
                          dl0_wih, dl0_whh, dl0_b, dl1_wih, dl1_whh, dl1_b,
                          fc_w, fc_b, dh0, dc0, dh1, dc1,
                          qb, rin, P0, P1, out, attn_out);
}

// round 14
// speedup vs baseline: 1.6284x; 1.0450x over previous
#include <cuda_runtime.h>
#include <cstddef>
typedef unsigned long long ull;

#define CB 256
#define CS 128
#define CT 128
#define CE 512
#define CH 1024
#define CHD 512
#define CV 256
#define MK (CS*CB)

#define OFF_XEMB   ((size_t)0)
#define OFF_PREA   (OFF_XEMB + (size_t)MK*CE)
#define OFF_PREB   (OFF_PREA + (size_t)MK*2048)
#define OFF_X1     (OFF_PREB + (size_t)MK*2048)
#define OFF_ENCOUT (OFF_X1 + (size_t)MK*CH)
#define OFF_ENCPROJ (OFF_ENCOUT + (size_t)MK*CH)
#define OFF_C0F    (OFF_ENCPROJ + (size_t)MK*CH)
#define OFF_C0B    (OFF_C0F + (size_t)CB*CHD)
#define OFF_C1F    (OFF_C0B + (size_t)CB*CHD)
#define OFF_C1B    (OFF_C1F + (size_t)CB*CHD)
#define OFF_DH0    (OFF_C1B + (size_t)CB*CHD)
#define OFF_DC0    (OFF_DH0 + (size_t)2*CB*CH)
#define OFF_DH1    (OFF_DC0 + (size_t)CB*CH)
#define OFF_DC1    (OFF_DH1 + (size_t)2*CB*CH)
#define OFF_Q      (OFF_DC1 + (size_t)CB*CH)
#define OFF_RIN    (OFF_Q + (size_t)CB*CH)
#define OFF_P0     (OFF_RIN + (size_t)CB*(CE+CH))
#define OFF_P1     (OFF_P0 + (size_t)20*CB*CH)
#define SCRATCH_FLOATS (OFF_P1 + (size_t)16*CB*CH)

__device__ float g_s[SCRATCH_FLOATS];
__device__ unsigned g_cnt;
__device__ unsigned g_gen;
__device__ unsigned g_tkt;

#define FMA2(d,a,b,c) asm("fma.rn.f32x2 %0, %1, %2, %3;" : "=l"(d) : "l"(a), "l"(b), "l"(c))
#define CPA8(dst,src) asm volatile("cp.async.ca.shared.global [%0], [%1], 8;" :: "r"(dst), "l"(src))
#define CPCOMMIT() asm volatile("cp.async.commit_group;")
#define CPWAIT1() asm volatile("cp.async.wait_group 1;")
#define CPWAIT0() asm volatile("cp.async.wait_group 0;")

__device__ __forceinline__ void upk(ull v, float& lo, float& hi){
    asm("mov.b64 {%0,%1}, %2;" : "=f"(lo), "=f"(hi) : "l"(v));
}
__device__ __forceinline__ float tanh_acc(float x){
    float xc = fminf(fmaxf(x, -7.90531110763549805f), 7.90531110763549805f);
    float x2 = xc*xc;
    float p = fmaf(x2, -2.76076847742355e-16f, 2.00018790482477e-13f);
    p = fmaf(x2, p, -8.60467152213735e-11f);
    p = fmaf(x2, p, 5.12229709037114e-08f);
    p = fmaf(x2, p, 1.48572235717979e-05f);
    p = fmaf(x2, p, 6.37261928875436e-04f);
    p = fmaf(x2, p, 4.89352455891786e-03f);
    p = p*xc;
    float q = fmaf(x2, 1.19825839466702e-06f, 1.18534705686654e-04f);
    q = fmaf(x2, q, 2.26843463243900e-03f);
    q = fmaf(x2, q, 4.89352518554385e-03f);
    return __fdividef(p, q);
}
__device__ __forceinline__ float sgf(float x){
    return __fdividef(1.f, 1.f + __expf(-x));
}

__device__ __forceinline__ void gbar()
{
    __syncthreads();
    if (threadIdx.x == 0) {
        __threadfence();
        unsigned gen = atomicAdd(&g_gen, 0u);
        if (atomicAdd(&g_cnt, 1u) == gridDim.x - 1u) {
            atomicExch(&g_cnt, 0u);
            atomicExch(&g_tkt, 0u);
            __threadfence();
            atomicAdd(&g_gen, 1u);
        } else {
            while (atomicAdd(&g_gen, 0u) == gen) __nanosleep(256);
        }
        __threadfence();
    }
    __syncthreads();
}

// ===== cp.async tile loader: NR weight rows (j-major, pitch 17 f2) + 64 act rows =====
template<int NR>
__device__ __forceinline__ void ld_tile(const float* __restrict__ W, int ldW, int GS, int jBase,
    const float* __restrict__ A, int lda, int bBase, int k0,
    float2* wb, float2* ab, int tid)
{
    int f = tid;
#pragma unroll
    for (int o = 0; o < NR/16; o++) {
        int row = f >> 4, col = f & 15;
        const float* s = W + (size_t)((row>>5)*GS + jBase + (row&31))*ldW + k0 + col*2;
        unsigned d = (unsigned)__cvta_generic_to_shared(wb + row*17 + col);
        CPA8(d, s);
        f += 256;
    }
    f = tid;
#pragma unroll
    for (int o = 0; o < 4; o++) {
        int row = f >> 4, col = f & 15;
        const float* s = A + (size_t)(bBase + row)*lda + k0 + col*2;
        unsigned d = (unsigned)__cvta_generic_to_shared(ab + row*17 + col);
        CPA8(d, s);
        f += 256;
    }
}

template<int NG>
__device__ __forceinline__ void comp_tile(const float2* wb, const float2* ab,
                                          ull (*acc)[8], int lane, int wid)
{
#pragma unroll
    for (int kk = 0; kk < 16; kk++) {
        ull w[NG];
#pragma unroll
        for (int g = 0; g < NG; g++) w[g] = *(const ull*)(wb + (g*32+lane)*17 + kk);
#pragma unroll
        for (int m = 0; m < 8; m++) {
            ull h = *(const ull*)(ab + (wid*8+m)*17 + kk);
#pragma unroll
            for (int g = 0; g < NG; g++) FMA2(acc[g][m], w[g], h, acc[g][m]);
        }
    }
}

// ===== double-buffered pipelined MM: acc[NG][8] over nch chunks of 32 k =====
template<int NG>
__device__ __forceinline__ void mm_pipe(const float* A, int lda, const float* W, int ldW,
    int GS, int jBase, int bBase, int kOff, int nch, ull (*acc)[8], float* sb)
{
    const int WB = NG*32*17;
    float2* wb0 = (float2*)sb;
    float2* ab0 = wb0 + WB;
    float2* wb1 = ab0 + 1088;
    float2* ab1 = wb1 + WB;
    int tid = threadIdx.x, lane = tid & 31, wid = tid >> 5;
    ld_tile<NG*32>(W, ldW, GS, jBase, A, lda, bBase, kOff, wb0, ab0, tid);
    CPCOMMIT();
    for (int c = 0; c < nch; c++) {
        if (c+1 < nch) {
            ld_tile<NG*32>(W, ldW, GS, jBase, A, lda, bBase, kOff + (c+1)*32,
                           (c&1)?wb0:wb1, (c&1)?ab0:ab1, tid);
            CPCOMMIT();
            CPWAIT1();
        } else CPWAIT0();
        __syncthreads();
        comp_tile<NG>((c&1)?wb1:wb0, (c&1)?ab1:ab0, acc, lane, wid);
        __syncthreads();
    }
}

// ===== plain GEMM unit: C[64m x 64n] = A.W^T + bias =====
__device__ __forceinline__ void gemm_u(const float* A, int lda, const float* W, int ldb,
    int K, const float* bias, float* C, long long ldc, int mBase, int nBase, float* sb)
{
    ull acc[2][8] = {};
    mm_pipe<2>(A, lda, W, ldb, 32, nBase, mBase, 0, K>>5, acc, sb);
    int lane = threadIdx.x & 31, wid = threadIdx.x >> 5;
#pragma unroll
    for (int s = 0; s < 2; s++) {
        int n = nBase + s*32 + lane;
        float bz = bias ? bias[n] : 0.f;
#pragma unroll
        for (int m = 0; m < 8; m++) {
            float lo, hi; upk(acc[s][m], lo, hi);
            C[(long long)(mBase + wid*8 + m)*ldc + n] = lo + hi + bz;
        }
    }
}

// ===== decoder gate partial unit: P[g][64b][32j] = A[:,kOff:kOff+512].W^T =====
__device__ __forceinline__ void gate_u(const float* A, int lda, int kOff,
    const float* W, int ldW, float* P, int jt, int bt, float* sb)
{
    ull acc[4][8] = {};
    mm_pipe<4>(A, lda, W, ldW, CH, jt*32, bt*64, kOff, 16, acc, sb);
    int lane = threadIdx.x & 31, wid = threadIdx.x >> 5;
    int j = jt*32 + lane;
#pragma unroll
    for (int g = 0; g < 4; g++)
#pragma unroll
        for (int m = 0; m < 8; m++) {
            float lo, hi; upk(acc[g][m], lo, hi);
            P[(size_t)(g*CB + bt*64 + wid*8 + m)*CH + j] = lo + hi;
        }
}

// ===== decoder cell finish: sum nseg partials + bias -> activations =====
__device__ __forceinline__ void fin(const float* P, int nseg, const float* bias,
                                    float* c, float* hout, int idx)
{
    int j2 = (idx & 511)*2, b = idx >> 9;
    float2 gs[4];
#pragma unroll
    for (int g = 0; g < 4; g++) {
        float2 s = *(const float2*)(bias + g*CH + j2);
        for (int sg = 0; sg < nseg; sg++) {
            float2 p = *(const float2*)(P + (size_t)((sg*4+g)*CB + b)*CH + j2);
            s.x += p.x; s.y += p.y;
        }
        gs[g] = s;
    }
    float2 cc = *(const float2*)(c + (size_t)b*CH + j2);
    float cnx = sgf(gs[1].x)*cc.x + sgf(gs[0].x)*tanh_acc(gs[2].x);
    float cny = sgf(gs[1].y)*cc.y + sgf(gs[0].y)*tanh_acc(gs[2].y);
    *(float2*)(c + (size_t)b*CH + j2) = make_float2(cnx, cny);
    *(float2*)(hout + (size_t)b*CH + j2) =
        make_float2(sgf(gs[3].x)*tanh_acc(cnx), sgf(gs[3].y)*tanh_acc(cny));
}

// ===== encoder cell unit (direct epilogue) =====
__device__ __forceinline__ void enc_u(const float* hprev, int lda, const float* whh,
    const float* pre, float* c, float* hout, long long hStride,
    int jt, int bt, bool first, float* sb)
{
    ull acc[4][8] = {};
    if (!first)
        mm_pipe<4>(hprev, lda, whh, CHD, CHD, jt*32, bt*64, 0, 16, acc, sb);
    int lane = threadIdx.x & 31, wid = threadIdx.x >> 5;
    int j = jt*32 + lane;
#pragma unroll
    for (int m = 0; m < 8; m++) {
        int b = bt*64 + wid*8 + m;
        const float* pr = pre + (size_t)b*2048;
        float gv[4];
#pragma unroll
        for (int g = 0; g < 4; g++) {
            float lo, hi; upk(acc[g][m], lo, hi);
            gv[g] = lo + hi + pr[g*CHD + j];
        }
        float cp = first ? 0.f : c[(size_t)b*CHD + j];
        float cn = sgf(gv[1])*cp + sgf(gv[0])*tanh_acc(gv[2]);
        c[(size_t)b*CHD + j] = cn;
        hout[(size_t)b*hStride + j] = sgf(gv[3])*tanh_acc(cn);
    }
}

// ===== attention for one batch row =====
__device__ __forceinline__ void dev_attn(int b,
    const float* __restrict__ encproj, const float* __restrict__ encout,
    const float* __restrict__ q, const float* __restrict__ w2,
    const int* __restrict__ src, const int* __restrict__ tgt,
    const float* __restrict__ dec_embed,
    float* __restrict__ rin, float* __restrict__ attn_out, int t, float* sm)
{
    float* sq = sm;
    float* sa = sm + CH;
    int tid = threadIdx.x;
    for (int h = tid; h < CH; h += 256) sq[h] = q[(size_t)b*CH + h];
    __syncthreads();

    int warp = tid >> 5, lane = tid & 31;
    for (int s = warp; s < CS; s += 8) {
        const float* ep = encproj + ((size_t)b*CS + s)*CH;
        float part = 0.f;
#pragma unroll
        for (int i = 0; i < 8; i++) {
            int h = i*128 + lane*4;
            float4 e4 = *(const float4*)(ep + h);
            float4 w4 = *(const float4*)(w2 + h);
            part = fmaf(tanh_acc(e4.x + sq[h]),   w4.x, part);
            part = fmaf(tanh_acc(e4.y + sq[h+1]), w4.y, part);
            part = fmaf(tanh_acc(e4.z + sq[h+2]), w4.z, part);
            part = fmaf(tanh_acc(e4.w + sq[h+3]), w4.w, part);
        }
#pragma unroll
        for (int o = 16; o; o >>= 1) part += __shfl_xor_sync(0xffffffffu, part, o);
        if (lane == 0) sa[s] = part;
    }
    __syncthreads();

    if (warp == 0) {
        const int* sr = src + b*CS;
        float e[4];
#pragma unroll
        for (int i = 0; i < 4; i++)
            e[i] = (sr[lane + 32*i] != 0) ? sa[lane + 32*i] : -1e30f;
        float m = fmaxf(fmaxf(e[0], e[1]), fmaxf(e[2], e[3]));
#pragma unroll
        for (int o = 16; o; o >>= 1) m = fmaxf(m, __shfl_xor_sync(0xffffffffu, m, o));
        float p[4], ssum = 0.f;
#pragma unroll
        for (int i = 0; i < 4; i++){ p[i] = __expf(e[i]-m); ssum += p[i]; }
#pragma unroll
        for (int o = 16; o; o >>= 1) ssum += __shfl_xor_sync(0xffffffffu, ssum, o);
        float inv = __fdividef(1.f, ssum);
        float* ao = attn_out + ((size_t)b*(CT-1) + t)*CS;
#pragma unroll
        for (int i = 0; i < 4; i++){ float v = p[i]*inv; sa[lane+32*i] = v; ao[lane+32*i] = v; }
    }
    __syncthreads();

    {
        int h = tid*4;
        float4 cx = make_float4(0.f, 0.f, 0.f, 0.f);
        const float* eo = encout + (size_t)b*CS*CH + h;
#pragma unroll 4
        for (int s = 0; s < CS; s++) {
            float a = sa[s];
            float4 v = *(const float4*)(eo + (size_t)s*CH);
            cx.x = fmaf(a, v.x, cx.x); cx.y = fmaf(a, v.y, cx.y);
            cx.z = fmaf(a, v.z, cx.z); cx.w = fmaf(a, v.w, cx.w);
        }
        *(float4*)(rin + (size_t)b*(CE+CH) + CE + h) = cx;
    }
    if (tid < CE/4) {
        int tok = tgt[b*CT + t];
        *(float4*)(rin + (size_t)b*(CE+CH) + tid*4) =
            *(const float4*)(dec_embed + (size_t)tok*CE + tid*4);
    }
    __syncthreads();
}

// ===== standalone kernels =====
__global__ void embed_enc(const int* __restrict__ src, const float* __restrict__ emb,
                          float* __restrict__ xemb)
{
    int i4 = blockIdx.x*blockDim.x + threadIdx.x;
    if (i4 >= MK*(CE/4)) return;
    int row = i4/(CE/4), q = i4%(CE/4);
    int t = row/CB, b = row%CB;
    int tok = src[b*CS + t];
    *(float4*)(xemb + (size_t)row*CE + 4*q) =
        *(const float4*)(emb + (size_t)tok*CE + 4*q);
}

__global__ __launch_bounds__(256, 2)
void gemm_k2(const float* A, int lda, const float* W, int ldb, int K,
             const float* bias, float* C, long long ldc)
{
    extern __shared__ float sb[];
    gemm_u(A, lda, W, ldb, K, bias, C, ldc, (int)blockIdx.y*64, (int)blockIdx.x*64, sb);
}

__global__ void init_dec(const float* __restrict__ x1, const float* __restrict__ encout,
                         const float* __restrict__ c0f, const float* __restrict__ c0b,
                         const float* __restrict__ c1f, const float* __restrict__ c1b,
                         float* __restrict__ dh0, float* __restrict__ dc0,
                         float* __restrict__ dh1, float* __restrict__ dc1)
{
    int idx = blockIdx.x*blockDim.x + threadIdx.x;
    if (idx >= CB*CH) return;
    int b = idx/CH, j = idx%CH;
    float h0, h1, cc0, cc1;
    if (j < CHD) {
        h0 = x1[((size_t)(CS-1)*CB + b)*CH + j];
        h1 = encout[((size_t)b*CS + CS-1)*CH + j];
        cc0 = c0f[(size_t)b*CHD + j];
        cc1 = c1f[(size_t)b*CHD + j];
    } else {
        h0 = x1[(size_t)b*CH + j];
        h1 = encout[(size_t)b*CS*CH + j];
        cc0 = c0b[(size_t)b*CHD + j - CHD];
        cc1 = c1b[(size_t)b*CHD + j - CHD];
    }
    dh0[idx] = h0; dc0[idx] = cc0;
    dh1[idx] = h1; dc1[idx] = cc1;
}

__global__ void zero_row0(float* __restrict__ out)
{
    int idx = blockIdx.x*blockDim.x + threadIdx.x;
    if (idx >= CB*CV) return;
    out[(size_t)(idx/CV)*CT*CV + idx%CV] = 0.f;
}

// ticket helper: variadic so commas in the body are safe
#define PHASE(N, ...) \
    for(;;){ \
        if (threadIdx.x == 0) s_u = (int)atomicAdd(&g_tkt, 1u); \
        __syncthreads(); \
        int u = s_u; \
        if (u >= (N)) break; \
        __VA_ARGS__ \
    } \
    gbar();

// ===== persistent encoder scan =====
__global__ __launch_bounds__(256, 2)
void enc_scan(const float* preA, const float* preB,
              const float* whhF, const float* whhB,
              float* cF, float* cB,
              float* hbase, long long tStride, long long hStride)
{
    extern __shared__ float sb[];
    __shared__ int s_u;
    for (int s = 0; s < CS; s++) {
        int tf = s, tb = CS-1-s;
        PHASE(128,
            int dir = u >> 6;
            int jt = (u >> 2) & 15;
            int bt = u & 3;
            int tt = dir ? tb : tf;
            const float* pre = dir ? preB + (size_t)tb*CB*2048 : preA + (size_t)tf*CB*2048;
            const float* whh = dir ? whhB : whhF;
            const float* hprev = hbase;
            if (s) { int tp = dir ? tb+1 : tf-1;
                     hprev = hbase + (size_t)tp*tStride + (dir ? CHD : 0); }
            float* c    = dir ? cB : cF;
            float* hout = hbase + (size_t)tt*tStride + (dir ? CHD : 0);
            enc_u(hprev, (int)hStride, whh, pre, c, hout, hStride, jt, bt, s == 0, sb);
        )
    }
}

// ===== persistent decoder loop =====
__global__ __launch_bounds__(256, 2)
void dec_loop(const float* encproj, const float* encout,
              const float* attn_w1, const float* attn_b1, const float* attn_w2,
              const int* src, const int* tgt, const float* dec_embed,
              const float* dl0_wih, const float* dl0_whh, const float* dl0_b,
              const float* dl1_wih, const float* dl1_whh, const float* dl1_b,
              const float* fc_w, const float* fc_b,
              float* dh0, float* dc0, float* dh1, float* dc1,
              float* qb, float* rin, float* P0, float* P1,
              float* out, float* attn_out)
{
    extern __shared__ float sb[];
    __shared__ int s_u;
    unsigned nb = gridDim.x;
    int tid = threadIdx.x;

    // initial q = h1 @ w1_q^T + b1
    PHASE(64,
        gemm_u(dh1, CH, attn_w1 + CH, 2*CH, CH, attn_b1, qb, CH,
               (u & 3)*64, (u >> 2)*64, sb);
    )

    for (int t = 0; t < CT-1; t++) {
        int cur = t & 1, nxt = 1 - cur;
        float* h0c = dh0 + (size_t)cur*CB*CH; float* h0n = dh0 + (size_t)nxt*CB*CH;
        float* h1c = dh1 + (size_t)cur*CB*CH; float* h1n = dh1 + (size_t)nxt*CB*CH;

        // attention
        PHASE(CB,
            dev_attn(u, encproj, encout, qb, attn_w2, src, tgt, dec_embed,
                     rin, attn_out, t, sb);
        )

        // cell0 gate partials: 5 segs x 128 tiles (K=512 each)
        PHASE(640,
            int sg = u >> 7;
            int r = u & 127;
            int jt = r >> 2;
            int bt = r & 3;
            if (sg < 3)
                gate_u(rin, CE+CH, sg*512, dl0_wih, CE+CH,
                       P0 + (size_t)sg*4*CB*CH, jt, bt, sb);
            else
                gate_u(h0c, CH, (sg-3)*512, dl0_whh, CH,
                       P0 + (size_t)sg*4*CB*CH, jt, bt, sb);
        )

        // cell0 finish
        for (int idx = blockIdx.x*256 + tid; idx < CB*CH/2; idx += nb*256)
            fin(P0, 5, dl0_b, dc0, h0n, idx);
        gbar();

        // cell1 gate partials: 4 segs x 128 tiles
        PHASE(512,
            int sg = u >> 7;
            int r = u & 127;
            int jt = r >> 2;
            int bt = r & 3;
            if (sg < 2)
                gate_u(h0n, CH, sg*512, dl1_wih, CH,
                       P1 + (size_t)sg*4*CB*CH, jt, bt, sb);
            else
                gate_u(h1c, CH, (sg-2)*512, dl1_whh, CH,
                       P1 + (size_t)sg*4*CB*CH, jt, bt, sb);
        )

        // cell1 finish
        for (int idx = blockIdx.x*256 + tid; idx < CB*CH/2; idx += nb*256)
            fin(P1, 4, dl1_b, dc1, h1n, idx);
        gbar();

        // logits + next q
        PHASE(80,
            if (u < 16)
                gemm_u(h1n, CH, fc_w, CH, CH, fc_b,
                       out + (size_t)(t+1)*CV, (long long)CT*CV,
                       (u & 3)*64, (u >> 2)*64, sb);
            else {
                int v = u - 16;
                gemm_u(h1n, CH, attn_w1 + CH, 2*CH, CH, attn_b1, qb, CH,
                       (v & 3)*64, (v >> 2)*64, sb);
            }
        )
    }
}

extern "C" void kernel_launch(void* const* d_in, const int* in_sizes, int n_in,
                              void* d_out, int out_size)
{
    const int*   src       = (const int*)  d_in[0];
    const int*   tgt       = (const int*)  d_in[1];
    const float* enc_embed = (const float*)d_in[2];
    const float* dec_embed = (const float*)d_in[3];
    const float* l0f_wih=(const float*)d_in[4],  *l0f_whh=(const float*)d_in[5],  *l0f_b=(const float*)d_in[6];
    const float* l0b_wih=(const float*)d_in[7],  *l0b_whh=(const float*)d_in[8],  *l0b_b=(const float*)d_in[9];
    const float* l1f_wih=(const float*)d_in[10], *l1f_whh=(const float*)d_in[11], *l1f_b=(const float*)d_in[12];
    const float* l1b_wih=(const float*)d_in[13], *l1b_whh=(const float*)d_in[14], *l1b_b=(const float*)d_in[15];
    const float* dl0_wih=(const float*)d_in[16], *dl0_whh=(const float*)d_in[17], *dl0_b=(const float*)d_in[18];
    const float* dl1_wih=(const float*)d_in[19], *dl1_whh=(const float*)d_in[20], *dl1_b=(const float*)d_in[21];
    const float* attn_w1=(const float*)d_in[22], *attn_b1=(const float*)d_in[23];
    const float* attn_w2=(const float*)d_in[24];
    const float* fc_w=(const float*)d_in[26],    *fc_b=(const float*)d_in[27];
    float* out = (float*)d_out;

    float* S;
    cudaGetSymbolAddress((void**)&S, g_s);
    float* xemb = S+OFF_XEMB;  float* preA = S+OFF_PREA;  float* preB = S+OFF_PREB;
    float* x1 = S+OFF_X1;      float* encout = S+OFF_ENCOUT; float* encproj = S+OFF_ENCPROJ;
    float* c0f = S+OFF_C0F;    float* c0b = S+OFF_C0B;
    float* c1f = S+OFF_C1F;    float* c1b = S+OFF_C1B;
    float* dh0 = S+OFF_DH0;    float* dc0 = S+OFF_DC0;
    float* dh1 = S+OFF_DH1;    float* dc1 = S+OFF_DC1;
    float* qb = S+OFF_Q;       float* rin = S+OFF_RIN;
    float* P0 = S+OFF_P0;      float* P1 = S+OFF_P1;
    float* attn_out = out + (size_t)CB*CT*CV;

    const int SMEM_BIG = 2*(4*32*17 + 64*17)*8;   // 52224 B
    const int SMEM_GEM = 2*(2*32*17 + 64*17)*8;   // 34816 B
    cudaFuncSetAttribute(enc_scan, cudaFuncAttributeMaxDynamicSharedMemorySize, SMEM_BIG);
    cudaFuncSetAttribute(dec_loop, cudaFuncAttributeMaxDynamicSharedMemorySize, SMEM_BIG);
    cudaFuncSetAttribute(gemm_k2, cudaFuncAttributeMaxDynamicSharedMemorySize, SMEM_GEM);

    int dev = 0; cudaGetDevice(&dev);
    int sms = 0; cudaDeviceGetAttribute(&sms, cudaDevAttrMultiProcessorCount, dev);
    int occ = 1;
    cudaOccupancyMaxActiveBlocksPerMultiprocessor(&occ, dec_loop, 256, SMEM_BIG);
    if (occ < 1) occ = 1;
    unsigned nb = (unsigned)(sms * occ);

    embed_enc<<<(MK*(CE/4)+255)/256, 256>>>(src, enc_embed, xemb);

    gemm_k2<<<dim3(2048/64, MK/64), 256, SMEM_GEM>>>(xemb, CE, l0f_wih, CE, CE, l0f_b, preA, 2048);
    gemm_k2<<<dim3(2048/64, MK/64), 256, SMEM_GEM>>>(xemb, CE, l0b_wih, CE, CE, l0b_b, preB, 2048);
    enc_scan<<<nb, 256, SMEM_BIG>>>(preA, preB, l0f_whh, l0b_whh, c0f, c0b,
                                    x1, (long long)CB*CH, (long long)CH);
    gemm_k2<<<dim3(2048/64, MK/64), 256, SMEM_GEM>>>(x1, CH, l1f_wih, CH, CH, l1f_b, preA, 2048);
    gemm_k2<<<dim3(2048/64, MK/64), 256, SMEM_GEM>>>(x1, CH, l1b_wih, CH, CH, l1b_b, preB, 2048);
    enc_scan<<<nb, 256, SMEM_BIG>>>(preA, preB, l1f_whh, l1b_whh, c1f, c1b,
                                    encout, (long long)CH, (long long)CS*CH);

    init_dec<<<(CB*CH+255)/256, 256>>>(x1, encout, c0f, c0b, c1f, c1b, dh0, dc0, dh1, dc1);
    gemm_k2<<<dim3(CH/64, MK/64), 256, SMEM_GEM>>>(encout, CH, attn_w1, 2*CH, CH, nullptr, encproj, CH);
    zero_row0<<<(CB*CV+255)/256, 256>>>(out);

    dec_loop<<<nb, 256, SMEM_BIG>>>(encproj, encout, attn_w1, attn_b1, attn_w2,
                                    src, tgt, dec_embed,
                                    dl0_wih, dl0_whh, dl0_b, dl1_wih, dl1_whh, dl1_b,
                                    fc_w, fc_b, dh0, dc0, dh1, dc1,
                                    qb, rin, P0, P1, out, attn_out);
}